// round 2
// baseline (speedup 1.0000x reference)
#include <cuda_runtime.h>
#include <cstdint>

// ---------------------------------------------------------------------------
// QMI Particle QAE encoder: batched statevector simulation.
// Blocks A,B,C: n=4 qubits, depth=1, latent=(0,1), trash=(2,3)
// Block D:      n=7 qubits, depth=4, latent=(0,1,2,3), trash=(4,5,6)
// Bit convention: qubit k lives at bit (n-1-k) of the amplitude index.
// ---------------------------------------------------------------------------

__device__ float g_wcos[40];
__device__ float g_wsin[40];

__global__ void prep_weights(const float* __restrict__ wA,
                             const float* __restrict__ wB,
                             const float* __restrict__ wC,
                             const float* __restrict__ wD) {
    int t = threadIdx.x;
    if (t >= 40) return;
    float w;
    if (t < 4)       w = wA[t];
    else if (t < 8)  w = wB[t - 4];
    else if (t < 12) w = wC[t - 8];
    else             w = wD[t - 12];
    float s, c;
    __sincosf(0.5f * w, &s, &c);
    g_wcos[t] = c;
    g_wsin[t] = s;
}

// ---------------------------------------------------------------------------
// n=4 block (A/B/C). One thread holds the full 16-amplitude state.
// ---------------------------------------------------------------------------
template <int BLK>
__device__ __forceinline__ void run4(const float* __restrict__ xr, int wbase,
                                     float& z0o, float& z1o) {
    constexpr int PT[3][4]  = {{5, 4, 35, 34}, {3, 33, 31, 2}, {28, 32, 15, 16}};
    constexpr int ETA[3][4] = {{9, 8, 45, 44}, {7, 43, 41, 6}, {38, 42, 19, 20}};
    constexpr int PHI[3][4] = {{13, 12, 55, 54}, {11, 53, 51, 10}, {48, 52, 23, 24}};

    float sr[16], si[16];
    sr[0] = 1.f; si[0] = 0.f;
    float tc[4][6];  // ce,se,cp,sp,cf,sf per qubit (reused by second layer)

    // ---- product state * folded CNOT chain: amp[b] = prod u_k[b_k ^ b_{k-1}]
#pragma unroll
    for (int k = 0; k < 4; k++) {
        float eta = __ldg(xr + ETA[BLK][k]);
        float pt  = __ldg(xr + PT[BLK][k]);
        float phi = __ldg(xr + PHI[BLK][k]);
        float ce, se, cp, sp, cf, sf;
        __sincosf(0.5f * eta, &se, &ce);
        __sincosf(0.5f * pt,  &sp, &cp);
        __sincosf(0.5f * phi, &sf, &cf);
        tc[k][0] = ce; tc[k][1] = se; tc[k][2] = cp;
        tc[k][3] = sp; tc[k][4] = cf; tc[k][5] = sf;
        // |q> = RZ(phi) RY(pt) RX(eta) |0>
        float ar = cp * ce, ai = sp * se, br = sp * ce, bi = -cp * se;
        float u0r = ar * cf + ai * sf, u0i = ai * cf - ar * sf;
        float u1r = br * cf - bi * sf, u1i = bi * cf + br * sf;
        const int step = 8 >> k;
#pragma unroll
        for (int p = 0; p < 16; p += 2 * step) {
            const int bprev = (k == 0) ? 0 : ((p >> (4 - k)) & 1);
            float g0r = bprev ? u1r : u0r, g0i = bprev ? u1i : u0i;
            float g1r = bprev ? u0r : u1r, g1i = bprev ? u0i : u1i;
            float x0 = sr[p], y0 = si[p];
            sr[p + step] = x0 * g1r - y0 * g1i;
            si[p + step] = x0 * g1i + y0 * g1r;
            sr[p] = x0 * g0r - y0 * g0i;
            si[p] = x0 * g0i + y0 * g0r;
        }
    }

    // ---- second layer: fused U = RX(phi) RY(pt) RZ(eta) per qubit
#pragma unroll
    for (int k = 0; k < 4; k++) {
        float ce = tc[k][0], se = tc[k][1], cp = tc[k][2];
        float sp = tc[k][3], cf = tc[k][4], sf = tc[k][5];
        float t1r = cf * cp, t1i = -sf * sp;
        float U00r = ce * t1r + se * t1i, U00i = ce * t1i - se * t1r;
        float t2r = -cf * sp, t2i = -sf * cp;
        float U01r = ce * t2r - se * t2i, U01i = ce * t2i + se * t2r;
        float t3r = cf * sp, t3i = -sf * cp;
        float U10r = ce * t3r + se * t3i, U10i = ce * t3i - se * t3r;
        float t4r = cf * cp, t4i = sf * sp;
        float U11r = ce * t4r - se * t4i, U11i = ce * t4i + se * t4r;
        const int step = 8 >> k;
#pragma unroll
        for (int i = 0; i < 16; i++) {
            if (((i >> (3 - k)) & 1) == 0) {
                const int i1 = i + step;
                float arr = sr[i], aii = si[i], brr = sr[i1], bii = si[i1];
                sr[i]  = U00r * arr - U00i * aii + U01r * brr - U01i * bii;
                si[i]  = U00r * aii + U00i * arr + U01r * bii + U01i * brr;
                sr[i1] = U10r * arr - U10i * aii + U11r * brr - U11i * bii;
                si[i1] = U10r * aii + U10i * arr + U11r * bii + U11i * brr;
            }
        }
    }

    // ---- depth loop (depth=1)
    // perm1: flip bits 3,2 iff parity(bits 1,0)   (CNOT(t,l) fan)
    {
        const int pj[4] = {1, 2, 5, 6};
#pragma unroll
        for (int q = 0; q < 4; q++) {
            const int j = pj[q], j2 = j ^ 12;
            float tr = sr[j], ti = si[j];
            sr[j] = sr[j2]; si[j] = si[j2];
            sr[j2] = tr;    si[j2] = ti;
        }
    }
    // RY(weights)
#pragma unroll
    for (int k = 0; k < 4; k++) {
        float c = g_wcos[wbase + k], s = g_wsin[wbase + k];
        const int step = 8 >> k;
#pragma unroll
        for (int i = 0; i < 16; i++) {
            if (((i >> (3 - k)) & 1) == 0) {
                const int i1 = i + step;
                float arr = sr[i], aii = si[i], brr = sr[i1], bii = si[i1];
                sr[i]  = c * arr - s * brr;  si[i]  = c * aii - s * bii;
                sr[i1] = s * arr + c * brr;  si[i1] = s * aii + c * bii;
            }
        }
    }
    // perm2: flip bits 1,0 iff parity(bits 3,2)   (CNOT(l,t) fan)
    {
        const int pj[4] = {4, 6, 8, 10};
#pragma unroll
        for (int q = 0; q < 4; q++) {
            const int j = pj[q], j2 = j ^ 3;
            float tr = sr[j], ti = si[j];
            sr[j] = sr[j2]; si[j] = si[j2];
            sr[j2] = tr;    si[j2] = ti;
        }
    }

    // ---- measure trash qubits 2 (bit1), 3 (bit0)
    float z0 = 0.f, z1 = 0.f;
#pragma unroll
    for (int i = 0; i < 16; i++) {
        float p = sr[i] * sr[i] + si[i] * si[i];
        z0 += ((i >> 1) & 1) ? -p : p;
        z1 += (i & 1) ? -p : p;
    }
    z0o = z0;
    z1o = z1;
}

__global__ void __launch_bounds__(256) kernelABC(const float* __restrict__ x,
                                                 float* __restrict__ out, int n) {
    int e = blockIdx.x * blockDim.x + threadIdx.x;
    if (e >= n) return;
    const float* xr = x + (size_t)e * 56;
    float za0, za1, zb0, zb1, zc0, zc1;
    run4<0>(xr, 0, za0, za1);
    run4<1>(xr, 4, zb0, zb1);
    run4<2>(xr, 8, zc0, zc1);
    float* o = out + (size_t)e * 9;
    o[0] = za0; o[1] = za1; o[2] = zb0; o[3] = zb1; o[4] = zc0; o[5] = zc1;
}

// ---------------------------------------------------------------------------
// n=7 block (D). 2 threads per element (adjacent lanes). Thread bit = qubit 0
// (bit 6 of the full amplitude index). Each thread holds 64 complex amps;
// local index j carries qubits 1..6 at bits 5..0.
// ---------------------------------------------------------------------------
__global__ void __launch_bounds__(256, 1) kernelD(const float* __restrict__ x,
                                                  float* __restrict__ out) {
    const unsigned FULL = 0xffffffffu;
    int gt = blockIdx.x * 256 + threadIdx.x;
    int e = gt >> 1;
    int t0 = gt & 1;
    const float* xr = x + (size_t)e * 56;

    constexpr int DPT[7] = {0, 14, 30, 26, 29, 27, 17};
    constexpr int DET[7] = {-1, 18, 40, 36, 39, 37, 21};
    constexpr int DPH[7] = {1, 22, 50, 46, 49, 47, 25};

    float sr[64], si[64];
    sr[0] = 1.f; si[0] = 0.f;

    // ---- product state build with folded CNOT chain
#pragma unroll
    for (int k = 0; k < 7; k++) {
        float eta = (DET[k] < 0) ? 0.f : __ldg(xr + DET[k]);
        float pt  = __ldg(xr + DPT[k]);
        float phi = __ldg(xr + DPH[k]);
        float ce, se, cp, sp, cf, sf;
        __sincosf(0.5f * eta, &se, &ce);
        __sincosf(0.5f * pt,  &sp, &cp);
        __sincosf(0.5f * phi, &sf, &cf);
        float ar = cp * ce, ai = sp * se, br = sp * ce, bi = -cp * se;
        float u0r = ar * cf + ai * sf, u0i = ai * cf - ar * sf;
        float u1r = br * cf - bi * sf, u1i = bi * cf + br * sf;
        if (k == 0) {
            // factor u0[b0], b0 = t0 (runtime)
            sr[0] = t0 ? u1r : u0r;
            si[0] = t0 ? u1i : u0i;
        } else if (k == 1) {
            // factor u1[b1 ^ t0]
            float g0r = t0 ? u1r : u0r, g0i = t0 ? u1i : u0i;  // b1 = 0
            float g1r = t0 ? u0r : u1r, g1i = t0 ? u0i : u1i;  // b1 = 1
            float x0 = sr[0], y0 = si[0];
            sr[32] = x0 * g1r - y0 * g1i;
            si[32] = x0 * g1i + y0 * g1r;
            sr[0] = x0 * g0r - y0 * g0i;
            si[0] = x0 * g0i + y0 * g0r;
        } else {
            const int step = 64 >> k;
#pragma unroll
            for (int p = 0; p < 64; p += 2 * step) {
                const int bprev = (p >> (7 - k)) & 1;  // b_{k-1}, compile-time
                float g0r = bprev ? u1r : u0r, g0i = bprev ? u1i : u0i;
                float g1r = bprev ? u0r : u1r, g1i = bprev ? u0i : u1i;
                float x0 = sr[p], y0 = si[p];
                sr[p + step] = x0 * g1r - y0 * g1i;
                si[p + step] = x0 * g1i + y0 * g1r;
                sr[p] = x0 * g0r - y0 * g0i;
                si[p] = x0 * g0i + y0 * g0r;
            }
        }
    }

    // ---- second layer, qubit 0 (cross-thread; eta[0]=0 so e^{±i a}=1)
    {
        float pt = __ldg(xr + DPT[0]);
        float phi = __ldg(xr + DPH[0]);
        float cp, sp, cf, sf;
        __sincosf(0.5f * pt,  &sp, &cp);
        __sincosf(0.5f * phi, &sf, &cf);
        float U00r = cf * cp, U00i = -sf * sp;
        float U01r = -cf * sp, U01i = -sf * cp;
        float U10r = cf * sp, U10i = -sf * cp;
        float U11r = cf * cp, U11i = sf * sp;
        // t0==0 -> new = U00*mine + U01*partner ; t0==1 -> U11*mine + U10*partner
        float Uar = t0 ? U11r : U00r, Uai = t0 ? U11i : U00i;
        float Ubr = t0 ? U10r : U01r, Ubi = t0 ? U10i : U01i;
#pragma unroll
        for (int j = 0; j < 64; j++) {
            float rr = __shfl_xor_sync(FULL, sr[j], 1);
            float ri = __shfl_xor_sync(FULL, si[j], 1);
            float arr = sr[j], aii = si[j];
            sr[j] = Uar * arr - Uai * aii + Ubr * rr - Ubi * ri;
            si[j] = Uar * aii + Uai * arr + Ubr * ri + Ubi * rr;
        }
    }
    // ---- second layer, qubits 1..6 (local)
#pragma unroll
    for (int k = 1; k < 7; k++) {
        float eta = __ldg(xr + DET[k]);
        float pt  = __ldg(xr + DPT[k]);
        float phi = __ldg(xr + DPH[k]);
        float ce, se, cp, sp, cf, sf;
        __sincosf(0.5f * eta, &se, &ce);
        __sincosf(0.5f * pt,  &sp, &cp);
        __sincosf(0.5f * phi, &sf, &cf);
        float t1r = cf * cp, t1i = -sf * sp;
        float U00r = ce * t1r + se * t1i, U00i = ce * t1i - se * t1r;
        float t2r = -cf * sp, t2i = -sf * cp;
        float U01r = ce * t2r - se * t2i, U01i = ce * t2i + se * t2r;
        float t3r = cf * sp, t3i = -sf * cp;
        float U10r = ce * t3r + se * t3i, U10i = ce * t3i - se * t3r;
        float t4r = cf * cp, t4i = sf * sp;
        float U11r = ce * t4r - se * t4i, U11i = ce * t4i + se * t4r;
        const int step = 64 >> k;
#pragma unroll
        for (int i = 0; i < 64; i++) {
            if (((i >> (6 - k)) & 1) == 0) {
                const int i1 = i + step;
                float arr = sr[i], aii = si[i], brr = sr[i1], bii = si[i1];
                sr[i]  = U00r * arr - U00i * aii + U01r * brr - U01i * bii;
                si[i]  = U00r * aii + U00i * arr + U01r * bii + U01i * brr;
                sr[i1] = U10r * arr - U10i * aii + U11r * brr - U11i * bii;
                si[i1] = U10r * aii + U10i * arr + U11r * bii + U11i * brr;
            }
        }
    }

    // ---- depth loop (depth = 4)
#pragma unroll 1
    for (int d = 0; d < 4; d++) {
        // perm1: flip latent bits (6,5,4,3) iff parity(trash bits 2,1,0).
        // bit 6 = thread bit -> exchange with XOR-1 partner; bits 5,4,3 local.
#pragma unroll
        for (int j = 0; j < 32; j++) {
            if (((j ^ (j >> 1) ^ (j >> 2)) & 1) == 1) {  // parity(j&7)==1
                const int j2 = j ^ 56;
                float ar = __shfl_xor_sync(FULL, sr[j2], 1);
                float ai = __shfl_xor_sync(FULL, si[j2], 1);
                float br = __shfl_xor_sync(FULL, sr[j], 1);
                float bi = __shfl_xor_sync(FULL, si[j], 1);
                sr[j] = ar;  si[j] = ai;
                sr[j2] = br; si[j2] = bi;
            }
        }
        // RY on qubit 0 (cross-thread)
        {
            float c = g_wcos[12 + d * 7 + 0];
            float s = g_wsin[12 + d * 7 + 0];
            float seff = t0 ? s : -s;
#pragma unroll
            for (int j = 0; j < 64; j++) {
                float rr = __shfl_xor_sync(FULL, sr[j], 1);
                float ri = __shfl_xor_sync(FULL, si[j], 1);
                sr[j] = c * sr[j] + seff * rr;
                si[j] = c * si[j] + seff * ri;
            }
        }
        // RY on qubits 1..6 (local)
#pragma unroll
        for (int k = 1; k < 7; k++) {
            float c = g_wcos[12 + d * 7 + k];
            float s = g_wsin[12 + d * 7 + k];
            const int step = 64 >> k;
#pragma unroll
            for (int i = 0; i < 64; i++) {
                if (((i >> (6 - k)) & 1) == 0) {
                    const int i1 = i + step;
                    float arr = sr[i], aii = si[i], brr = sr[i1], bii = si[i1];
                    sr[i]  = c * arr - s * brr;  si[i]  = c * aii - s * bii;
                    sr[i1] = s * arr + c * brr;  si[i1] = s * aii + c * bii;
                }
            }
        }
        // perm2: flip trash bits (2,1,0) iff parity(latent) = t0 ^ parity(j>>3)
#pragma unroll
        for (int j = 0; j < 64; j++) {
            if ((j & 4) == 0) {
                const int j2 = j ^ 7;
                const int pc = ((j >> 3) ^ (j >> 4) ^ (j >> 5)) & 1;
                bool sw = (pc != t0);
                float ar = sr[j], ai = si[j], br = sr[j2], bi = si[j2];
                sr[j]  = sw ? br : ar;  si[j]  = sw ? bi : ai;
                sr[j2] = sw ? ar : br;  si[j2] = sw ? ai : bi;
            }
        }
    }

    // ---- measure trash qubits 4,5,6 (bits 2,1,0 of j; independent of t0)
    float z4 = 0.f, z5 = 0.f, z6 = 0.f;
#pragma unroll
    for (int j = 0; j < 64; j++) {
        float p = sr[j] * sr[j] + si[j] * si[j];
        z4 += ((j >> 2) & 1) ? -p : p;
        z5 += ((j >> 1) & 1) ? -p : p;
        z6 += (j & 1) ? -p : p;
    }
    z4 += __shfl_xor_sync(FULL, z4, 1);
    z5 += __shfl_xor_sync(FULL, z5, 1);
    z6 += __shfl_xor_sync(FULL, z6, 1);

    if (t0 == 0) {
        float* o = out + (size_t)e * 9 + 6;
        o[0] = z4; o[1] = z5; o[2] = z6;
    }
}

// ---------------------------------------------------------------------------
extern "C" void kernel_launch(void* const* d_in, const int* in_sizes, int n_in,
                              void* d_out, int out_size) {
    const float* x  = (const float*)d_in[0];
    const float* wA = (const float*)d_in[1];
    const float* wB = (const float*)d_in[2];
    const float* wC = (const float*)d_in[3];
    const float* wD = (const float*)d_in[4];
    float* out = (float*)d_out;
    int n = in_sizes[0] / 56;

    prep_weights<<<1, 64>>>(wA, wB, wC, wD);

    int blocksD = (2 * n + 255) / 256;
    kernelD<<<blocksD, 256>>>(x, out);

    int blocksABC = (n + 255) / 256;
    kernelABC<<<blocksABC, 256>>>(x, out, n);
}

// round 3
// speedup vs baseline: 1.2710x; 1.2710x over previous
#include <cuda_runtime.h>
#include <cstdint>

// ---------------------------------------------------------------------------
// QMI Particle QAE encoder — packed f32x2 statevector simulation.
// State stored as (re,im) packed in one 64-bit register pair; all gate math
// uses fma.rn.f32x2 / mul.rn.f32x2 (FFMA2 path, 2x FFMA throughput on B300).
// Blocks A,B,C: n=4, depth=1, latent=(0,1), trash=(2,3)
// Block D:      n=7, depth=4, latent=(0,1,2,3), trash=(4,5,6), 2 threads/elem
// ---------------------------------------------------------------------------

typedef unsigned long long u64;

__device__ __forceinline__ u64 pk2(float lo, float hi) {
    u64 r; asm("mov.b64 %0, {%1, %2};" : "=l"(r) : "f"(lo), "f"(hi)); return r;
}
__device__ __forceinline__ void upk2(u64 v, float& lo, float& hi) {
    asm("mov.b64 {%0, %1}, %2;" : "=f"(lo), "=f"(hi) : "l"(v));
}
__device__ __forceinline__ u64 swp2(u64 v) {  // (a,b) -> (b,a): register rename, free
    float a, b; upk2(v, a, b); return pk2(b, a);
}
__device__ __forceinline__ u64 ffma2(u64 a, u64 b, u64 c) {
    u64 d; asm("fma.rn.f32x2 %0, %1, %2, %3;" : "=l"(d) : "l"(a), "l"(b), "l"(c)); return d;
}
__device__ __forceinline__ u64 fmul2(u64 a, u64 b) {
    u64 d; asm("mul.rn.f32x2 %0, %1, %2;" : "=l"(d) : "l"(a), "l"(b)); return d;
}

// complex coefficient, pre-splatted: r=(re,re), i=(-im,im)
struct C2 { u64 r, i; };
__device__ __forceinline__ C2 mkc(float re, float im) {
    C2 c; c.r = pk2(re, re); c.i = pk2(-im, im); return c;
}
__device__ __forceinline__ u64 craw(const C2& c) {  // packed raw (re, im)
    float re, d0, d1, im; upk2(c.r, re, d0); upk2(c.i, d1, im); return pk2(re, im);
}
// complex multiply: c * x   (swp is free)
__device__ __forceinline__ u64 cmul(const C2& c, u64 x) {
    return ffma2(c.r, x, fmul2(c.i, swp2(x)));
}
__device__ __forceinline__ u64 cmad(const C2& c, u64 x, u64 acc) {
    return ffma2(c.r, x, ffma2(c.i, swp2(x), acc));
}
__device__ __forceinline__ u64 shfl1(u64 v) { return __shfl_xor_sync(0xffffffffu, v, 1); }

// Build coefficients for one qubit: q[bprev][b] = u[b ^ bprev] * z[b]
// u = RZ(phi) RY(pt) RX(eta) |0>   (layer-1 ket),  z = layer-2 RZ(eta) phases.
struct QC { C2 q00, q01, q10, q11; float cp, sp, cf, sf; };

__device__ __forceinline__ QC make_qc(float eta, float pt, float phi) {
    float ce, se, cp, sp, cf, sf;
    __sincosf(0.5f * eta, &se, &ce);
    __sincosf(0.5f * pt,  &sp, &cp);
    __sincosf(0.5f * phi, &sf, &cf);
    float ar = cp * ce, ai = sp * se, br = sp * ce, bi = -cp * se;
    float u0r = ar * cf + ai * sf, u0i = ai * cf - ar * sf;
    float u1r = br * cf - bi * sf, u1i = bi * cf + br * sf;
    QC q;
    q.q00 = mkc(u0r * ce + u0i * se, -u0r * se + u0i * ce);  // u0 * (ce,-se)
    q.q01 = mkc(u1r * ce - u1i * se,  u1r * se + u1i * ce);  // u1 * (ce, se)
    q.q10 = mkc(u1r * ce + u1i * se, -u1r * se + u1i * ce);  // u1 * (ce,-se)
    q.q11 = mkc(u0r * ce - u0i * se,  u0r * se + u0i * ce);  // u0 * (ce, se)
    q.cp = cp; q.sp = sp; q.cf = cf; q.sf = sf;
    return q;
}

// Layer-2 per-qubit sweep: RY(pt) then RX(phi), each as 3 lifted shears.
// RY: [c,-s;s,c] = [1,t;0,1][1,0;s,1][1,t;0,1],  t = -s/(1+c)
// RX: same with imaginary shears: a += i*t*b  ->  ffma2(pk(-t,t), swp(b), a)
template <int NV, int BP>
__device__ __forceinline__ void sweep_ryrx(u64* v, float cp, float sp, float cf, float sf) {
    const int step = 1 << BP;
    float ty = __fdividef(-sp, 1.f + cp);
    float tx = __fdividef(-sf, 1.f + cf);
    u64 pty = pk2(ty, ty), psy = pk2(sp, sp);
    u64 ptx = pk2(-tx, tx), psx = pk2(sf, -sf);
#pragma unroll
    for (int i = 0; i < NV; i++) {
        if (((i >> BP) & 1) == 0) {
            u64 a = v[i], b = v[i + step];
            a = ffma2(pty, b, a);
            b = ffma2(psy, a, b);
            a = ffma2(pty, b, a);
            a = ffma2(ptx, swp2(b), a);
            b = ffma2(psx, swp2(a), b);
            a = ffma2(ptx, swp2(b), a);
            v[i] = a; v[i + step] = b;
        }
    }
}

template <int NV, int BP>
__device__ __forceinline__ void sweep_ry(u64* v, float c, float s) {
    const int step = 1 << BP;
    float t = __fdividef(-s, 1.f + c);
    u64 pt_ = pk2(t, t), ps_ = pk2(s, s);
#pragma unroll
    for (int i = 0; i < NV; i++) {
        if (((i >> BP) & 1) == 0) {
            u64 a = v[i], b = v[i + step];
            a = ffma2(pt_, b, a);
            b = ffma2(ps_, a, b);
            a = ffma2(pt_, b, a);
            v[i] = a; v[i + step] = b;
        }
    }
}

// ---------------------------------------------------------------------------
// n=4 block (A/B/C): one thread holds the 16-amp state.
// ---------------------------------------------------------------------------
template <int BLK>
__device__ __forceinline__ void run4p(const float* __restrict__ xr,
                                      const float* __restrict__ w,
                                      float& z0o, float& z1o) {
    constexpr int PT[3][4]  = {{5, 4, 35, 34}, {3, 33, 31, 2}, {28, 32, 15, 16}};
    constexpr int ETA[3][4] = {{9, 8, 45, 44}, {7, 43, 41, 6}, {38, 42, 19, 20}};
    constexpr int PHI[3][4] = {{13, 12, 55, 54}, {11, 53, 51, 10}, {48, 52, 23, 24}};

    u64 v[16];
    float tcp[4], tsp[4], tcf[4], tsf[4];
    {
        QC q = make_qc(__ldg(xr + ETA[BLK][0]), __ldg(xr + PT[BLK][0]), __ldg(xr + PHI[BLK][0]));
        tcp[0] = q.cp; tsp[0] = q.sp; tcf[0] = q.cf; tsf[0] = q.sf;
        v[0] = craw(q.q00);
        v[8] = craw(q.q01);
    }
#pragma unroll
    for (int k = 1; k < 4; k++) {
        QC q = make_qc(__ldg(xr + ETA[BLK][k]), __ldg(xr + PT[BLK][k]), __ldg(xr + PHI[BLK][k]));
        tcp[k] = q.cp; tsp[k] = q.sp; tcf[k] = q.cf; tsf[k] = q.sf;
        const int step = 8 >> k;
#pragma unroll
        for (int p = 0; p < 16; p += 2 * step) {
            const bool bp = (p >> (4 - k)) & 1;
            C2 g0 = bp ? q.q10 : q.q00;
            C2 g1 = bp ? q.q11 : q.q01;
            v[p + step] = cmul(g1, v[p]);
            v[p]        = cmul(g0, v[p]);
        }
    }
    // layer 2 (RZ folded into build): RY then RX per qubit
    sweep_ryrx<16, 3>(v, tcp[0], tsp[0], tcf[0], tsf[0]);
    sweep_ryrx<16, 2>(v, tcp[1], tsp[1], tcf[1], tsf[1]);
    sweep_ryrx<16, 1>(v, tcp[2], tsp[2], tcf[2], tsf[2]);
    sweep_ryrx<16, 0>(v, tcp[3], tsp[3], tcf[3], tsf[3]);

    // perm1: flip bits 3,2 iff parity(bits 1,0)
    {
        const int pj[4] = {1, 2, 5, 6};
#pragma unroll
        for (int qd = 0; qd < 4; qd++) {
            const int j = pj[qd], j2 = j ^ 12;
            u64 t = v[j]; v[j] = v[j2]; v[j2] = t;
        }
    }
    // RY(weights)
    {
        float c, s;
        __sincosf(0.5f * __ldg(w + 0), &s, &c); sweep_ry<16, 3>(v, c, s);
        __sincosf(0.5f * __ldg(w + 1), &s, &c); sweep_ry<16, 2>(v, c, s);
        __sincosf(0.5f * __ldg(w + 2), &s, &c); sweep_ry<16, 1>(v, c, s);
        __sincosf(0.5f * __ldg(w + 3), &s, &c); sweep_ry<16, 0>(v, c, s);
    }
    // perm2: flip bits 1,0 iff parity(bits 3,2)
    {
        const int pj[4] = {4, 6, 8, 10};
#pragma unroll
        for (int qd = 0; qd < 4; qd++) {
            const int j = pj[qd], j2 = j ^ 3;
            u64 t = v[j]; v[j] = v[j2]; v[j2] = t;
        }
    }
    // measure trash qubits 2 (bit1), 3 (bit0)
    float acc[4] = {0.f, 0.f, 0.f, 0.f};
#pragma unroll
    for (int i = 0; i < 16; i++) {
        float xr_, xi_; upk2(v[i], xr_, xi_);
        acc[i & 3] = fmaf(xr_, xr_, fmaf(xi_, xi_, acc[i & 3]));
    }
    z0o = acc[0] + acc[1] - acc[2] - acc[3];
    z1o = acc[0] - acc[1] + acc[2] - acc[3];
}

// ---------------------------------------------------------------------------
// n=7 block (D): 2 adjacent lanes per element; thread bit = qubit 0 (bit 6).
// Local index j carries qubits 1..6 at bits 5..0. 64 packed amps per thread.
// ---------------------------------------------------------------------------
__device__ __forceinline__ void runD(const float* __restrict__ xr,
                                     const float* __restrict__ wD,
                                     int t0, float* __restrict__ outp) {
    constexpr int DPT[7] = {0, 14, 30, 26, 29, 27, 17};
    constexpr int DET[7] = {-1, 18, 40, 36, 39, 37, 21};
    constexpr int DPH[7] = {1, 22, 50, 46, 49, 47, 25};

    u64 v[64];
    // ---- build: product state * folded CNOT chain * folded layer-2 RZ
    {
        QC q = make_qc(0.f, __ldg(xr + DPT[0]), __ldg(xr + DPH[0]));
        v[0] = craw(t0 ? q.q01 : q.q00);
    }
    {
        QC q = make_qc(__ldg(xr + DET[1]), __ldg(xr + DPT[1]), __ldg(xr + DPH[1]));
        C2 ga = t0 ? q.q10 : q.q00;
        C2 gb = t0 ? q.q11 : q.q01;
        v[32] = cmul(gb, v[0]);
        v[0]  = cmul(ga, v[0]);
    }
#pragma unroll
    for (int k = 2; k < 7; k++) {
        QC q = make_qc(__ldg(xr + DET[k]), __ldg(xr + DPT[k]), __ldg(xr + DPH[k]));
        const int step = 64 >> k;
#pragma unroll
        for (int p = 0; p < 64; p += 2 * step) {
            const bool bp = (p >> (7 - k)) & 1;
            C2 g0 = bp ? q.q10 : q.q00;
            C2 g1 = bp ? q.q11 : q.q01;
            v[p + step] = cmul(g1, v[p]);
            v[p]        = cmul(g0, v[p]);
        }
    }
    // ---- layer 2, qubit 0 (cross-thread, eta=0): W = RX(phi) RY(pt)
    {
        float cp, sp, cf, sf;
        __sincosf(0.5f * __ldg(xr + DPT[0]), &sp, &cp);
        __sincosf(0.5f * __ldg(xr + DPH[0]), &sf, &cf);
        C2 Ua = t0 ? mkc(cf * cp,  sf * sp) : mkc(cf * cp, -sf * sp);
        C2 Ub = t0 ? mkc(cf * sp, -sf * cp) : mkc(-cf * sp, -sf * cp);
#pragma unroll
        for (int j = 0; j < 64; j++) {
            u64 r = shfl1(v[j]);
            v[j] = cmad(Ua, v[j], cmul(Ub, r));
        }
    }
    // ---- layer 2, qubits 1..6 (local): RY+RX lifted sweeps
    {
        float cp, sp, cf, sf;
#define L2Q(K, BPv)                                                     \
        __sincosf(0.5f * __ldg(xr + DPT[K]), &sp, &cp);                 \
        __sincosf(0.5f * __ldg(xr + DPH[K]), &sf, &cf);                 \
        sweep_ryrx<64, BPv>(v, cp, sp, cf, sf);
        L2Q(1, 5) L2Q(2, 4) L2Q(3, 3) L2Q(4, 2) L2Q(5, 1) L2Q(6, 0)
#undef L2Q
    }
    // ---- depth loop (depth = 4)
#pragma unroll 1
    for (int d = 0; d < 4; d++) {
        const float* wd = wD + d * 7;
        float c0, s0;
        __sincosf(0.5f * __ldg(wd + 0), &s0, &c0);
        u64 pc = pk2(c0, c0);
        float se = t0 ? s0 : -s0;
        u64 pse = pk2(se, se);
        // fused (perm1: flip bits 6,5,4,3 iff parity(bits 2..0)) + RY(q0):
        //   parity0 j : out = c*v[j] + se*shfl(v[j])
        //   parity1 j : out[j] = c*shfl(v[j^56]) + se*v[j^56]  (pairwise)
#pragma unroll
        for (int j = 0; j < 64; j++) {
            const int par = (j ^ (j >> 1) ^ (j >> 2)) & 1;
            if (par == 0) {
                u64 r = shfl1(v[j]);
                v[j] = ffma2(pc, v[j], fmul2(pse, r));
            } else if (j < 32) {
                const int j2 = j ^ 56;
                u64 r1 = shfl1(v[j2]);
                u64 r2 = shfl1(v[j]);
                u64 nj  = ffma2(pc, r1, fmul2(pse, v[j2]));
                u64 nj2 = ffma2(pc, r2, fmul2(pse, v[j]));
                v[j] = nj; v[j2] = nj2;
            }
        }
        // RY on qubits 1..6 (local, lifted)
        float c, s;
        __sincosf(0.5f * __ldg(wd + 1), &s, &c); sweep_ry<64, 5>(v, c, s);
        __sincosf(0.5f * __ldg(wd + 2), &s, &c); sweep_ry<64, 4>(v, c, s);
        __sincosf(0.5f * __ldg(wd + 3), &s, &c); sweep_ry<64, 3>(v, c, s);
        __sincosf(0.5f * __ldg(wd + 4), &s, &c); sweep_ry<64, 2>(v, c, s);
        __sincosf(0.5f * __ldg(wd + 5), &s, &c); sweep_ry<64, 1>(v, c, s);
        __sincosf(0.5f * __ldg(wd + 6), &s, &c); sweep_ry<64, 0>(v, c, s);
        // perm2: flip trash bits 2,1,0 iff parity(latent) = t0 ^ parity(bits 5..3)
#pragma unroll
        for (int j = 0; j < 64; j++) {
            if ((j & 4) == 0) {
                const int j2 = j ^ 7;
                const int pc2 = ((j >> 3) ^ (j >> 4) ^ (j >> 5)) & 1;
                bool sw = (pc2 != t0);
                u64 a = v[j], b = v[j2];
                v[j]  = sw ? b : a;
                v[j2] = sw ? a : b;
            }
        }
    }
    // ---- measure trash qubits 4,5,6 (bits 2,1,0)
    float acc[8] = {0.f, 0.f, 0.f, 0.f, 0.f, 0.f, 0.f, 0.f};
#pragma unroll
    for (int j = 0; j < 64; j++) {
        float xr_, xi_; upk2(v[j], xr_, xi_);
        acc[j & 7] = fmaf(xr_, xr_, fmaf(xi_, xi_, acc[j & 7]));
    }
    float z4 = acc[0] + acc[1] + acc[2] + acc[3] - acc[4] - acc[5] - acc[6] - acc[7];
    float z5 = acc[0] + acc[1] - acc[2] - acc[3] + acc[4] + acc[5] - acc[6] - acc[7];
    float z6 = acc[0] - acc[1] + acc[2] - acc[3] + acc[4] - acc[5] + acc[6] - acc[7];
    z4 += __shfl_xor_sync(0xffffffffu, z4, 1);
    z5 += __shfl_xor_sync(0xffffffffu, z5, 1);
    z6 += __shfl_xor_sync(0xffffffffu, z6, 1);
    if (t0 == 0) { outp[0] = z4; outp[1] = z5; outp[2] = z6; }
}

// ---------------------------------------------------------------------------
// Single fused kernel: first blocksD blocks run D (2 threads/elem), the rest
// run A+B+C (1 thread/elem). Grid-level split -> no warp divergence.
// ---------------------------------------------------------------------------
__global__ void __launch_bounds__(256, 1)
qae_fused(const float* __restrict__ x,
          const float* __restrict__ wA, const float* __restrict__ wB,
          const float* __restrict__ wC, const float* __restrict__ wD,
          float* __restrict__ out, int n, int blocksD) {
    if ((int)blockIdx.x < blocksD) {
        int gt = (int)blockIdx.x * 256 + (int)threadIdx.x;
        int e = gt >> 1;
        if (e >= n) return;
        int t0 = gt & 1;
        runD(x + (size_t)e * 56, wD, t0, out + (size_t)e * 9 + 6);
    } else {
        int e = ((int)blockIdx.x - blocksD) * 256 + (int)threadIdx.x;
        if (e >= n) return;
        const float* xr = x + (size_t)e * 56;
        float za0, za1, zb0, zb1, zc0, zc1;
        run4p<0>(xr, wA, za0, za1);
        run4p<1>(xr, wB, zb0, zb1);
        run4p<2>(xr, wC, zc0, zc1);
        float* o = out + (size_t)e * 9;
        o[0] = za0; o[1] = za1; o[2] = zb0;
        o[3] = zb1; o[4] = zc0; o[5] = zc1;
    }
}

extern "C" void kernel_launch(void* const* d_in, const int* in_sizes, int n_in,
                              void* d_out, int out_size) {
    const float* x  = (const float*)d_in[0];
    const float* wA = (const float*)d_in[1];
    const float* wB = (const float*)d_in[2];
    const float* wC = (const float*)d_in[3];
    const float* wD = (const float*)d_in[4];
    float* out = (float*)d_out;
    int n = in_sizes[0] / 56;

    int blocksD   = (2 * n + 255) / 256;
    int blocksABC = (n + 255) / 256;
    qae_fused<<<blocksD + blocksABC, 256>>>(x, wA, wB, wC, wD, out, n, blocksD);
}